// round 17
// baseline (speedup 1.0000x reference)
#include <cuda_runtime.h>
#include <cuda_fp16.h>
#include <stdint.h>
#include <math.h>

#define NB 1024
#define NS 1024
#define DI 128
#define DS 64
#define KSEL 8

typedef unsigned long long ull;

__device__ __half g_Hh[(size_t)NB * NS * DS];     // 128 MB (fp16 H)
__device__ float g_scores[(size_t)NB * NS];       // 4 MB

// pre-split, pre-swizzled weights (written once per call by k0_setup)
__device__ uint4 g_w1h[1024], g_w1l[1024];        // 16 KB each
__device__ uint4 g_w2h[512],  g_w2l[512];         // 8 KB each
__device__ float g_wt[65];                        // w~ = W2*qm, [64] = b2.qm
__device__ float g_b1s[64], g_b2s[64];

// ======================= helpers =======================
__device__ __forceinline__ uint32_t smem_u32(const void* p) {
    uint32_t a;
    asm("{ .reg .u64 t; cvta.to.shared.u64 t, %1; cvt.u32.u64 %0, t; }" : "=r"(a) : "l"(p));
    return a;
}
// 2-way fp16 split: fp32 pair -> packed half2 (hi, lo residual). 22 mantissa
// bits; 3-term product error ~2^-22 (fp32-class for this problem).
__device__ __forceinline__ void split2h(float a, float b, uint32_t& hi, uint32_t& lo) {
    __half2 h = __float22half2_rn(make_float2(a, b));
    float2 hf = __half22float2(h);
    __half2 l = __float22half2_rn(make_float2(a - hf.x, b - hf.y));
    hi = *reinterpret_cast<uint32_t*>(&h);
    lo = *reinterpret_cast<uint32_t*>(&l);
}
__device__ __forceinline__ void ldm4(uint32_t r[4], uint32_t addr) {
    asm volatile("ldmatrix.sync.aligned.m8n8.x4.shared.b16 {%0,%1,%2,%3}, [%4];"
        : "=r"(r[0]), "=r"(r[1]), "=r"(r[2]), "=r"(r[3]) : "r"(addr));
}
__device__ __forceinline__ void mma16816(float c[4], const uint32_t a[4],
                                         uint32_t b0, uint32_t b1) {
    asm volatile(
        "mma.sync.aligned.m16n8k16.row.col.f32.f16.f16.f32 "
        "{%0,%1,%2,%3}, {%4,%5,%6,%7}, {%8,%9}, {%0,%1,%2,%3};"
        : "+f"(c[0]), "+f"(c[1]), "+f"(c[2]), "+f"(c[3])
        : "r"(a[0]), "r"(a[1]), "r"(a[2]), "r"(a[3]), "r"(b0), "r"(b1));
}

// ======================= K0: one-time weight split =======================
__global__ __launch_bounds__(256) void k0_setup(
    const float* __restrict__ W1, const float* __restrict__ b1,
    const float* __restrict__ W2, const float* __restrict__ b2,
    const float* __restrict__ q)
{
    const int tid = threadIdx.x, blk = blockIdx.x;
    {   // W1 -> [n][128k] split tiles, swizzled (idx = n*16 + (kc^(n&7)))
        int task = blk * 256 + tid;
        int n = task & 63, kc = task >> 6;
        uint32_t h[4], l[4];
        #pragma unroll
        for (int j = 0; j < 4; j++) {
            float v0 = W1[(size_t)(kc * 8 + j * 2 + 0) * DS + n];
            float v1 = W1[(size_t)(kc * 8 + j * 2 + 1) * DS + n];
            split2h(v0, v1, h[j], l[j]);
        }
        int idx = n * 16 + (kc ^ (n & 7));
        g_w1h[idx] = make_uint4(h[0], h[1], h[2], h[3]);
        g_w1l[idx] = make_uint4(l[0], l[1], l[2], l[3]);
    }
    if (tid < 128) {   // W2 -> [n][64k] (idx = n*8 + (kc^(n&7)))
        int task = blk * 128 + tid;
        int n = task & 63, kc = task >> 6;
        uint32_t h[4], l[4];
        #pragma unroll
        for (int j = 0; j < 4; j++) {
            float v0 = W2[(size_t)(kc * 8 + j * 2 + 0) * DS + n];
            float v1 = W2[(size_t)(kc * 8 + j * 2 + 1) * DS + n];
            split2h(v0, v1, h[j], l[j]);
        }
        int idx = n * 8 + (kc ^ (n & 7));
        g_w2h[idx] = make_uint4(h[0], h[1], h[2], h[3]);
        g_w2l[idx] = make_uint4(l[0], l[1], l[2], l[3]);
    }
    if (blk == 0) {
        // w~ = W2*qm: 4 threads per output n, 16 coalesced floats each + shfl
        int n = tid >> 2, qtr = tid & 3;
        float acc = 0.0f;
        #pragma unroll
        for (int j = 0; j < 16; j += 4) {
            int d = qtr * 16 + j;
            float4 w = *(const float4*)(W2 + (size_t)n * DS + d);
            acc += w.x * 0.5f * (q[d]     + q[DS + d]);
            acc += w.y * 0.5f * (q[d + 1] + q[DS + d + 1]);
            acc += w.z * 0.5f * (q[d + 2] + q[DS + d + 2]);
            acc += w.w * 0.5f * (q[d + 3] + q[DS + d + 3]);
        }
        acc += __shfl_xor_sync(0xffffffffu, acc, 1);
        acc += __shfl_xor_sync(0xffffffffu, acc, 2);
        if (qtr == 0) g_wt[n] = acc;
        if (tid < DS) { g_b1s[tid] = b1[tid]; g_b2s[tid] = b2[tid]; }
    }
    if (blk == 1 && tid == 0) {   // b2.qm (tiny; parallel with block 0)
        float acc = 0.0f;
        #pragma unroll 8
        for (int d = 0; d < DS; d++)
            acc += b2[d] * (0.5f * (q[d] + q[DS + d]));
        g_wt[64] = acc;
    }
}

// ======================= K1: register-resident split-fp16 HMMA MLP ==========
// GEMM1: 3-term split (scores need fp32-class T).
// GEMM2: 2-term (Th x (W2h + W2l)).
static constexpr int SM_W1H = 0,     SM_W1L = 16384;
static constexpr int SM_W2H = 32768, SM_W2L = 40960;
static constexpr int SM_WT = 49152,  SM_B1S = 49424, SM_B2S = 49680;
static constexpr int SM_TOTAL = 49936;

__global__ __launch_bounds__(256, 2) void k1_mlp(
    const float* __restrict__ X)
{
    extern __shared__ __align__(16) char sm[];
    const uint32_t sb = smem_u32(sm);
    float* wt  = (float*)(sm + SM_WT);
    float* b1s = (float*)(sm + SM_B1S);
    float* b2s = (float*)(sm + SM_B2S);

    const int tid  = threadIdx.x;
    const int warp = tid >> 5, lane = tid & 31;
    const int grp  = lane >> 2, qd = lane & 3;
    const int seg  = lane >> 3, ri = lane & 7;
    const int rA = warp * 16 + grp, rB = rA + 8;
    const size_t row0 = (size_t)blockIdx.x * 128;

    // ---- prologue: L2-hot copy of pre-split weights into smem ----
    #pragma unroll
    for (int i = 0; i < 4; i++) {
        int idx = tid + 256 * i;
        ((uint4*)(sm + SM_W1H))[idx] = g_w1h[idx];
        ((uint4*)(sm + SM_W1L))[idx] = g_w1l[idx];
    }
    #pragma unroll
    for (int i = 0; i < 2; i++) {
        int idx = tid + 256 * i;
        ((uint4*)(sm + SM_W2H))[idx] = g_w2h[idx];
        ((uint4*)(sm + SM_W2L))[idx] = g_w2l[idx];
    }
    if (tid < 65) wt[tid] = g_wt[tid];
    if (tid < 64) { b1s[tid] = g_b1s[tid]; b2s[tid] = g_b2s[tid]; }

    const float* XrA = X + (row0 + rA) * DI + 2 * qd;
    const float* XrB = X + (row0 + rB) * DI + 2 * qd;

    float2 pa0 = *(const float2*)(XrA);
    float2 pb0 = *(const float2*)(XrB);
    float2 pa8 = *(const float2*)(XrA + 8);
    float2 pb8 = *(const float2*)(XrB + 8);

    __syncthreads();   // the ONLY barrier

    float c1[8][4];
    #pragma unroll
    for (int nt = 0; nt < 8; nt++)
        #pragma unroll
        for (int j = 0; j < 4; j++) c1[nt][j] = 0.0f;

    // ================= GEMM1: K=128, 8 chunks, 3 terms =================
    #pragma unroll
    for (int ks = 0; ks < 8; ks++) {
        float2 ca0 = pa0, cb0 = pb0, ca8 = pa8, cb8 = pb8;
        if (ks < 7) {
            int o = 16 * (ks + 1);
            pa0 = *(const float2*)(XrA + o);
            pb0 = *(const float2*)(XrB + o);
            pa8 = *(const float2*)(XrA + o + 8);
            pb8 = *(const float2*)(XrB + o + 8);
        }
        uint32_t ah[4], al[4];
        split2h(ca0.x, ca0.y, ah[0], al[0]);
        split2h(cb0.x, cb0.y, ah[1], al[1]);
        split2h(ca8.x, ca8.y, ah[2], al[2]);
        split2h(cb8.x, cb8.y, ah[3], al[3]);

        uint32_t bh[16], bl[16];
        #pragma unroll
        for (int g = 0; g < 4; g++) {
            int n = (g * 2 + (seg >> 1)) * 8 + ri;
            int c = 2 * ks + (seg & 1);
            uint32_t off = (uint32_t)n * 256 + (uint32_t)((c ^ (n & 7)) << 4);
            ldm4(&bh[g * 4], sb + SM_W1H + off);
            ldm4(&bl[g * 4], sb + SM_W1L + off);
        }
        #pragma unroll
        for (int nt = 0; nt < 8; nt++)
            mma16816(c1[nt], ah, bh[nt * 2], bh[nt * 2 + 1]);
        #pragma unroll
        for (int nt = 0; nt < 8; nt++)
            mma16816(c1[nt], ah, bl[nt * 2], bl[nt * 2 + 1]);
        #pragma unroll
        for (int nt = 0; nt < 8; nt++)
            mma16816(c1[nt], al, bh[nt * 2], bh[nt * 2 + 1]);
    }

    // ---- relu + b1 -> fp32 scores (w~) + fp16 T fragments (hi only) ----
    uint32_t th01[8], th23[8];
    {
        float pA = 0.0f, pB = 0.0f;
        #pragma unroll
        for (int nt = 0; nt < 8; nt++) {
            int c0 = nt * 8 + qd * 2;
            float t0 = fmaxf(c1[nt][0] + b1s[c0],     0.0f);
            float t1 = fmaxf(c1[nt][1] + b1s[c0 + 1], 0.0f);
            float t2 = fmaxf(c1[nt][2] + b1s[c0],     0.0f);
            float t3 = fmaxf(c1[nt][3] + b1s[c0 + 1], 0.0f);
            pA += t0 * wt[c0] + t1 * wt[c0 + 1];
            pB += t2 * wt[c0] + t3 * wt[c0 + 1];
            __half2 h01 = __floats2half2_rn(t0, t1);
            __half2 h23 = __floats2half2_rn(t2, t3);
            th01[nt] = *reinterpret_cast<uint32_t*>(&h01);
            th23[nt] = *reinterpret_cast<uint32_t*>(&h23);
        }
        pA += __shfl_xor_sync(0xffffffffu, pA, 1);
        pA += __shfl_xor_sync(0xffffffffu, pA, 2);
        pB += __shfl_xor_sync(0xffffffffu, pB, 1);
        pB += __shfl_xor_sync(0xffffffffu, pB, 2);
        if (qd == 0) {
            float b2qm = wt[64];
            g_scores[row0 + rA] = (pA + b2qm) * 0.125f;
            g_scores[row0 + rB] = (pB + b2qm) * 0.125f;
        }
    }

    // ====== GEMM2: H = Th @ (W2h + W2l) + b2 (K=64, 2 terms, T in regs) ======
    float c2[8][4];
    #pragma unroll
    for (int nt = 0; nt < 8; nt++)
        #pragma unroll
        for (int j = 0; j < 4; j++) c2[nt][j] = 0.0f;

    #pragma unroll
    for (int ks = 0; ks < 4; ks++) {
        uint32_t ah[4] = {th01[2 * ks], th23[2 * ks], th01[2 * ks + 1], th23[2 * ks + 1]};
        uint32_t bh[16], bl[16];
        #pragma unroll
        for (int g = 0; g < 4; g++) {
            int n = (g * 2 + (seg >> 1)) * 8 + ri;
            int c = 2 * ks + (seg & 1);
            uint32_t off = (uint32_t)n * 128 + (uint32_t)((c ^ (n & 7)) << 4);
            ldm4(&bh[g * 4], sb + SM_W2H + off);
            ldm4(&bl[g * 4], sb + SM_W2L + off);
        }
        #pragma unroll
        for (int nt = 0; nt < 8; nt++)
            mma16816(c2[nt], ah, bh[nt * 2], bh[nt * 2 + 1]);
        #pragma unroll
        for (int nt = 0; nt < 8; nt++)
            mma16816(c2[nt], ah, bl[nt * 2], bl[nt * 2 + 1]);
    }

    // ---- epilogue: +b2, fp16 H store (half2 per 2 cols) ----
    #pragma unroll
    for (int nt = 0; nt < 8; nt++) {
        int c0 = nt * 8 + qd * 2;
        __half2 hA = __floats2half2_rn(c2[nt][0] + b2s[c0], c2[nt][1] + b2s[c0 + 1]);
        __half2 hB = __floats2half2_rn(c2[nt][2] + b2s[c0], c2[nt][3] + b2s[c0 + 1]);
        *(__half2*)&g_Hh[(row0 + rA) * DS + c0] = hA;
        *(__half2*)&g_Hh[(row0 + rB) * DS + c0] = hB;
    }
}

// ======================= K2: softmax + ctx + top-8 + gather ==================
__global__ __launch_bounds__(256) void k2_attn(
    const float* __restrict__ mask,
    float* __restrict__ out_sel, float* __restrict__ out_ctx,
    float* __restrict__ out_attn)
{
    __shared__ float sms[NS];
    __shared__ float ss[NS];
    __shared__ float aw[NS];
    __shared__ float red[256];
    __shared__ int   redi[256];
    __shared__ float cpart[32][DS + 1];
    __shared__ int   idxs[KSEL];

    const int t = threadIdx.x;
    const int b = blockIdx.x;
    const float* sc = g_scores + (size_t)b * NS;
    const float* mk = mask + (size_t)b * NS;

    float lmax = -INFINITY;
    #pragma unroll
    for (int u = 0; u < 4; u++) {
        int s = t + 256 * u;
        float v = sc[s];
        float m = (mk[s] > 0.5f) ? v : -INFINITY;
        sms[s] = m;
        lmax = fmaxf(lmax, m);
    }
    red[t] = lmax;
    __syncthreads();
    for (int off = 128; off > 0; off >>= 1) {
        if (t < off) red[t] = fmaxf(red[t], red[t + off]);
        __syncthreads();
    }
    const float mx = red[0];
    const bool allm = !(mx > -INFINITY);
    __syncthreads();

    float lsum = 0.0f;
    #pragma unroll
    for (int u = 0; u < 4; u++) {
        int s = t + 256 * u;
        float m = sms[s];
        float e;
        if (allm)                e = 1.0f;
        else if (m == -INFINITY) e = 0.0f;
        else                     e = expf(m - mx);
        aw[s] = e;
        lsum += e;
    }
    red[t] = lsum;
    __syncthreads();
    for (int off = 128; off > 0; off >>= 1) {
        if (t < off) red[t] += red[t + off];
        __syncthreads();
    }
    const float inv = 1.0f / red[0];
    __syncthreads();
    #pragma unroll
    for (int u = 0; u < 4; u++) {
        int s = t + 256 * u;
        float w = aw[s] * inv;
        aw[s] = w;
        out_attn[(size_t)b * NS + s] = w;
        ss[s] = allm ? 0.0f : sms[s];
    }
    __syncthreads();

    // ctx: fp16 H, 16B loads, 32 s-parts x 8 d-groups of 8, 8 indep FMA chains
    const __half* Hb = g_Hh + (size_t)b * NS * DS;
    {
        const int part = t >> 3, dg = t & 7;   // s-part 0..31, d-group 0..7
        const int s0 = part * 32;
        const uint4* src = (const uint4*)(Hb + (size_t)s0 * DS + dg * 8);
        float a0 = 0.f, a1 = 0.f, a2 = 0.f, a3 = 0.f;
        float a4 = 0.f, a5 = 0.f, a6 = 0.f, a7 = 0.f;
        #pragma unroll 8
        for (int i = 0; i < 32; i += 2) {
            uint4 v0 = src[(size_t)i * 8];       // DS/8 = 8 uint4 per row
            uint4 v1 = src[(size_t)(i + 1) * 8];
            float w0 = aw[s0 + i], w1 = aw[s0 + i + 1];
            float2 q0 = __half22float2(*(__half2*)&v0.x);
            float2 q1 = __half22float2(*(__half2*)&v0.y);
            float2 q2 = __half22float2(*(__half2*)&v0.z);
            float2 q3 = __half22float2(*(__half2*)&v0.w);
            a0 += w0 * q0.x; a1 += w0 * q0.y;
            a2 += w0 * q1.x; a3 += w0 * q1.y;
            a4 += w0 * q2.x; a5 += w0 * q2.y;
            a6 += w0 * q3.x; a7 += w0 * q3.y;
            q0 = __half22float2(*(__half2*)&v1.x);
            q1 = __half22float2(*(__half2*)&v1.y);
            q2 = __half22float2(*(__half2*)&v1.z);
            q3 = __half22float2(*(__half2*)&v1.w);
            a0 += w1 * q0.x; a1 += w1 * q0.y;
            a2 += w1 * q1.x; a3 += w1 * q1.y;
            a4 += w1 * q2.x; a5 += w1 * q2.y;
            a6 += w1 * q3.x; a7 += w1 * q3.y;
        }
        float* cp = &cpart[part][dg * 8];
        cp[0] = a0; cp[1] = a1; cp[2] = a2; cp[3] = a3;
        cp[4] = a4; cp[5] = a5; cp[6] = a6; cp[7] = a7;
    }
    __syncthreads();
    if (t < DS) {
        float acc = 0.0f;
        #pragma unroll
        for (int p = 0; p < 32; p++) acc += cpart[p][t];
        out_ctx[(size_t)b * DS + t] = acc;
    }

    for (int it = 0; it < KSEL; it++) {
        float bv = -INFINITY; int bi = 0x7fffffff;
        #pragma unroll
        for (int u = 0; u < 4; u++) {
            int s = t + 256 * u;
            float v = ss[s];
            if (v > bv || (v == bv && s < bi)) { bv = v; bi = s; }
        }
        red[t] = bv; redi[t] = bi;
        __syncthreads();
        for (int off = 128; off > 0; off >>= 1) {
            if (t < off) {
                float v2 = red[t + off]; int i2 = redi[t + off];
                if (v2 > red[t] || (v2 == red[t] && i2 < redi[t])) { red[t] = v2; redi[t] = i2; }
            }
            __syncthreads();
        }
        if (t == 0) { idxs[it] = redi[0]; ss[redi[0]] = -INFINITY; }
        __syncthreads();
    }

    for (int e = t; e < KSEL * DS; e += 256) {
        int j = e >> 6, d = e & 63;
        out_sel[((size_t)b * KSEL + j) * DS + d] =
            __half2float(Hb[(size_t)idxs[j] * DS + d]);
    }
}

// ============================================================================
extern "C" void kernel_launch(void* const* d_in, const int* in_sizes, int n_in,
                              void* d_out, int out_size) {
    const float* X    = (const float*)d_in[0];
    const float* mask = (const float*)d_in[1];
    const float* W1   = (const float*)d_in[2];
    const float* b1   = (const float*)d_in[3];
    const float* W2   = (const float*)d_in[4];
    const float* b2   = (const float*)d_in[5];
    const float* q    = (const float*)d_in[6];

    float* out      = (float*)d_out;
    float* out_sel  = out;
    float* out_ctx  = out + (size_t)NB * KSEL * DS;
    float* out_attn = out_ctx + (size_t)NB * DS;

    cudaFuncSetAttribute(k1_mlp, cudaFuncAttributeMaxDynamicSharedMemorySize, SM_TOTAL);

    k0_setup<<<4, 256>>>(W1, b1, W2, b2, q);
    k1_mlp<<<8192, 256, SM_TOTAL>>>(X);
    k2_attn<<<NB, 256>>>(mask, out_sel, out_ctx, out_attn);
}